// round 1
// baseline (speedup 1.0000x reference)
#include <cuda_runtime.h>

// TensorReduce_88536455839845 — NeRF over-compositing.
// rgba:     [65536, 192, 4] f32  (d_in[0])
// distance: [65536, 192]    f32  (d_in[1])
// out:      [65536, 3]      f32
//
// One warp per ray. 6 chunks of 32 samples. Warp-scan exclusive cumprod for
// transmittance with a cross-chunk carry; warp tree-reduce for RGB.

#define NR_RAYS    65536
#define NR_SAMPLES 192
#define NR_CHUNKS  (NR_SAMPLES / 32)

#define EPS_DIST   1e-5f
#define EPS_ALPHA  1e-8f
#define FAR_DELTA  1e4f

__device__ __forceinline__ float fast_sigmoid(float x) {
    return 1.0f / (1.0f + __expf(-x));
}

__global__ __launch_bounds__(256) void composite_kernel(
    const float4* __restrict__ rgba,     // [N, S] float4
    const float*  __restrict__ dist,     // [N, S]
    float*        __restrict__ out)      // [N, 3]
{
    const unsigned FULL = 0xffffffffu;
    int gwarp = (blockIdx.x * blockDim.x + threadIdx.x) >> 5;
    int lane  = threadIdx.x & 31;
    if (gwarp >= NR_RAYS) return;

    const float4* ray_rgba = rgba + (size_t)gwarp * NR_SAMPLES;
    const float*  ray_dist = dist + (size_t)gwarp * NR_SAMPLES;

    float carry = 1.0f;           // transmittance entering this chunk
    float r_acc = 0.0f, g_acc = 0.0f, b_acc = 0.0f;

    #pragma unroll
    for (int k = 0; k < NR_CHUNKS; ++k) {
        int s = (k << 5) + lane;

        float4 v  = ray_rgba[s];                 // coalesced 512B per warp
        float  d0 = ray_dist[s];                 // coalesced
        float  d1 = (s + 1 < NR_SAMPLES) ? ray_dist[s + 1] : d0;  // shifted window, L1 hit

        float delta = (s == NR_SAMPLES - 1) ? FAR_DELTA : fabsf(d1 - d0);

        float density = (d0 < EPS_DIST) ? 0.0f : v.w;
        density = fmaxf(density, 0.0f);

        float alpha = 1.0f - __expf(-delta * density);
        float oma   = 1.0f - alpha + EPS_ALPHA;  // strictly > 0

        // Inclusive warp scan (product)
        float incl = oma;
        #pragma unroll
        for (int off = 1; off < 32; off <<= 1) {
            float t = __shfl_up_sync(FULL, incl, off);
            if (lane >= off) incl *= t;
        }
        // Exclusive shift
        float excl = __shfl_up_sync(FULL, incl, 1);
        if (lane == 0) excl = 1.0f;

        float trans = carry * excl;
        float w     = alpha * trans;

        r_acc = fmaf(w, fast_sigmoid(v.x), r_acc);
        g_acc = fmaf(w, fast_sigmoid(v.y), g_acc);
        b_acc = fmaf(w, fast_sigmoid(v.z), b_acc);

        carry *= __shfl_sync(FULL, incl, 31);
    }

    // Warp tree-reduce the 3 accumulators
    #pragma unroll
    for (int off = 16; off > 0; off >>= 1) {
        r_acc += __shfl_down_sync(FULL, r_acc, off);
        g_acc += __shfl_down_sync(FULL, g_acc, off);
        b_acc += __shfl_down_sync(FULL, b_acc, off);
    }

    if (lane == 0) {
        float* o = out + (size_t)gwarp * 3;
        o[0] = r_acc;
        o[1] = g_acc;
        o[2] = b_acc;
    }
}

extern "C" void kernel_launch(void* const* d_in, const int* in_sizes, int n_in,
                              void* d_out, int out_size) {
    const float4* rgba = (const float4*)d_in[0];
    const float*  dist = (const float*)d_in[1];
    float* out = (float*)d_out;

    // 65536 rays, 1 warp/ray, 8 warps/block -> 8192 blocks
    dim3 block(256);
    dim3 grid((NR_RAYS * 32) / 256);
    composite_kernel<<<grid, block>>>(rgba, dist, out);
}

// round 2
// speedup vs baseline: 1.0914x; 1.0914x over previous
#include <cuda_runtime.h>

// TensorReduce_88536455839845 — NeRF over-compositing, R2.
// One warp per ray; all 6 chunks' loads hoisted up front (MLP=12/thread),
// the 6 warp-scans interleaved for ILP, distance neighbor via shfl.
//
// rgba:     [65536, 192, 4] f32  (d_in[0])
// distance: [65536, 192]    f32  (d_in[1])
// out:      [65536, 3]      f32

#define NR_RAYS    65536
#define NR_SAMPLES 192
#define NR_CHUNKS  6

#define EPS_DIST   1e-5f
#define EPS_ALPHA  1e-8f
#define FAR_DELTA  1e4f

__device__ __forceinline__ float fast_sigmoid(float x) {
    return __fdividef(1.0f, 1.0f + __expf(-x));
}

__global__ __launch_bounds__(256) void composite_kernel(
    const float4* __restrict__ rgba,     // [N, S] float4
    const float*  __restrict__ dist,     // [N, S]
    float*        __restrict__ out)      // [N, 3]
{
    const unsigned FULL = 0xffffffffu;
    int gwarp = (blockIdx.x * blockDim.x + threadIdx.x) >> 5;
    int lane  = threadIdx.x & 31;
    if (gwarp >= NR_RAYS) return;

    const float4* ray_rgba = rgba + (size_t)gwarp * NR_SAMPLES;
    const float*  ray_dist = dist + (size_t)gwarp * NR_SAMPLES;

    // ---- Phase 1: issue ALL global loads up front (streaming, evict-first) ----
    float4 v[NR_CHUNKS];
    float  d0[NR_CHUNKS];
    #pragma unroll
    for (int k = 0; k < NR_CHUNKS; ++k) {
        int s = (k << 5) + lane;
        v[k]  = __ldcs(&ray_rgba[s]);
        d0[k] = __ldcs(&ray_dist[s]);
    }

    // ---- Phase 2: alpha / (1-alpha+eps) per chunk ----
    float alpha[NR_CHUNKS];
    float incl[NR_CHUNKS];
    #pragma unroll
    for (int k = 0; k < NR_CHUNKS; ++k) {
        // d[s+1]: neighbor lane's d0; lane 31 takes next chunk's lane-0 value.
        float nxt = (k < NR_CHUNKS - 1) ? __shfl_sync(FULL, d0[k + 1], 0) : d0[k];
        float d1  = __shfl_down_sync(FULL, d0[k], 1);
        if (lane == 31) d1 = nxt;

        bool  last  = (k == NR_CHUNKS - 1) && (lane == 31);
        float delta = last ? FAR_DELTA : fabsf(d1 - d0[k]);

        float density = (d0[k] < EPS_DIST) ? 0.0f : fmaxf(v[k].w, 0.0f);

        float a  = 1.0f - __expf(-delta * density);
        alpha[k] = a;
        incl[k]  = 1.0f - a + EPS_ALPHA;        // strictly > 0
    }

    // ---- Phase 3: 6 independent inclusive product scans, interleaved ----
    // (outer loop over offset -> 6-wide ILP on the SHFL dependency chain)
    #pragma unroll
    for (int off = 1; off < 32; off <<= 1) {
        #pragma unroll
        for (int k = 0; k < NR_CHUNKS; ++k) {
            float t = __shfl_up_sync(FULL, incl[k], off);
            if (lane >= off) incl[k] *= t;
        }
    }

    // Exclusive value + chunk totals (independent, before carry chain)
    float excl[NR_CHUNKS], tot[NR_CHUNKS];
    #pragma unroll
    for (int k = 0; k < NR_CHUNKS; ++k) {
        float e = __shfl_up_sync(FULL, incl[k], 1);
        excl[k] = (lane == 0) ? 1.0f : e;
        tot[k]  = __shfl_sync(FULL, incl[k], 31);
    }

    // ---- Phase 4: carry chain (6 dependent FMULs) + weighted accumulate ----
    float carry = 1.0f;
    float r_acc = 0.0f, g_acc = 0.0f, b_acc = 0.0f;
    #pragma unroll
    for (int k = 0; k < NR_CHUNKS; ++k) {
        float w = alpha[k] * carry * excl[k];
        r_acc = fmaf(w, fast_sigmoid(v[k].x), r_acc);
        g_acc = fmaf(w, fast_sigmoid(v[k].y), g_acc);
        b_acc = fmaf(w, fast_sigmoid(v[k].z), b_acc);
        carry *= tot[k];
    }

    // ---- Warp tree-reduce the 3 accumulators ----
    #pragma unroll
    for (int off = 16; off > 0; off >>= 1) {
        r_acc += __shfl_down_sync(FULL, r_acc, off);
        g_acc += __shfl_down_sync(FULL, g_acc, off);
        b_acc += __shfl_down_sync(FULL, b_acc, off);
    }

    if (lane == 0) {
        float* o = out + (size_t)gwarp * 3;
        o[0] = r_acc;
        o[1] = g_acc;
        o[2] = b_acc;
    }
}

extern "C" void kernel_launch(void* const* d_in, const int* in_sizes, int n_in,
                              void* d_out, int out_size) {
    const float4* rgba = (const float4*)d_in[0];
    const float*  dist = (const float*)d_in[1];
    float* out = (float*)d_out;

    dim3 block(256);
    dim3 grid((NR_RAYS * 32) / 256);   // 1 warp per ray
    composite_kernel<<<grid, block>>>(rgba, dist, out);
}

// round 3
// speedup vs baseline: 1.2464x; 1.1420x over previous
#include <cuda_runtime.h>

// TensorReduce_88536455839845 — NeRF over-compositing, R3.
// One warp per ray. Key change vs R2: __launch_bounds__(256, 4) releases the
// register cap (32 -> ~64) so ptxas can keep ALL 12 global loads front-batched
// (true MLP=12/thread) instead of sinking them into the scan dependency chain.
//
// rgba:     [65536, 192, 4] f32  (d_in[0])
// distance: [65536, 192]    f32  (d_in[1])
// out:      [65536, 3]      f32

#define NR_RAYS    65536
#define NR_SAMPLES 192
#define NR_CHUNKS  6

#define EPS_DIST   1e-5f
#define EPS_ALPHA  1e-8f
#define FAR_DELTA  1e4f

__device__ __forceinline__ float fast_sigmoid(float x) {
    return __fdividef(1.0f, 1.0f + __expf(-x));
}

__global__ __launch_bounds__(256, 4) void composite_kernel(
    const float4* __restrict__ rgba,     // [N, S] float4
    const float*  __restrict__ dist,     // [N, S]
    float*        __restrict__ out)      // [N, 3]
{
    const unsigned FULL = 0xffffffffu;
    int gwarp = (blockIdx.x * blockDim.x + threadIdx.x) >> 5;
    int lane  = threadIdx.x & 31;
    if (gwarp >= NR_RAYS) return;

    const float4* ray_rgba = rgba + (size_t)gwarp * NR_SAMPLES;
    const float*  ray_dist = dist + (size_t)gwarp * NR_SAMPLES;

    // ---- Phase 1: ALL global loads up front (streaming, evict-first) ----
    // With the 64-reg budget these live in registers; 12 outstanding
    // loads/thread fully cover DRAM latency.
    float4 v[NR_CHUNKS];
    float  d0[NR_CHUNKS];
    #pragma unroll
    for (int k = 0; k < NR_CHUNKS; ++k) {
        int s = (k << 5) + lane;
        v[k]  = __ldcs(&ray_rgba[s]);
        d0[k] = __ldcs(&ray_dist[s]);
    }

    // ---- Phase 2: alpha / (1-alpha+eps) per chunk ----
    float alpha[NR_CHUNKS];
    float incl[NR_CHUNKS];
    #pragma unroll
    for (int k = 0; k < NR_CHUNKS; ++k) {
        // d[s+1]: neighbor lane's value; lane 31 takes next chunk's lane 0.
        float nxt = (k < NR_CHUNKS - 1) ? __shfl_sync(FULL, d0[k + 1], 0) : d0[k];
        float d1  = __shfl_down_sync(FULL, d0[k], 1);
        if (lane == 31) d1 = nxt;

        bool  last  = (k == NR_CHUNKS - 1) && (lane == 31);
        float delta = last ? FAR_DELTA : fabsf(d1 - d0[k]);

        float density = (d0[k] < EPS_DIST) ? 0.0f : fmaxf(v[k].w, 0.0f);

        float a  = 1.0f - __expf(-delta * density);
        alpha[k] = a;
        incl[k]  = 1.0f - a + EPS_ALPHA;        // strictly > 0
    }

    // ---- Phase 3: 6 independent inclusive product scans, interleaved ----
    // Outer loop over shuffle offset -> 6-wide ILP on the SHFL latency chain.
    #pragma unroll
    for (int off = 1; off < 32; off <<= 1) {
        #pragma unroll
        for (int k = 0; k < NR_CHUNKS; ++k) {
            float t = __shfl_up_sync(FULL, incl[k], off);
            if (lane >= off) incl[k] *= t;
        }
    }

    // Exclusive value + per-chunk totals (all independent)
    float excl[NR_CHUNKS], tot[NR_CHUNKS];
    #pragma unroll
    for (int k = 0; k < NR_CHUNKS; ++k) {
        float e = __shfl_up_sync(FULL, incl[k], 1);
        excl[k] = (lane == 0) ? 1.0f : e;
        tot[k]  = __shfl_sync(FULL, incl[k], 31);
    }

    // ---- Phase 4: carry chain (6 dependent FMULs) + weighted accumulate ----
    float carry = 1.0f;
    float r_acc = 0.0f, g_acc = 0.0f, b_acc = 0.0f;
    #pragma unroll
    for (int k = 0; k < NR_CHUNKS; ++k) {
        float w = alpha[k] * carry * excl[k];
        r_acc = fmaf(w, fast_sigmoid(v[k].x), r_acc);
        g_acc = fmaf(w, fast_sigmoid(v[k].y), g_acc);
        b_acc = fmaf(w, fast_sigmoid(v[k].z), b_acc);
        carry *= tot[k];
    }

    // ---- Warp tree-reduce the 3 accumulators ----
    #pragma unroll
    for (int off = 16; off > 0; off >>= 1) {
        r_acc += __shfl_down_sync(FULL, r_acc, off);
        g_acc += __shfl_down_sync(FULL, g_acc, off);
        b_acc += __shfl_down_sync(FULL, b_acc, off);
    }

    if (lane == 0) {
        float* o = out + (size_t)gwarp * 3;
        o[0] = r_acc;
        o[1] = g_acc;
        o[2] = b_acc;
    }
}

extern "C" void kernel_launch(void* const* d_in, const int* in_sizes, int n_in,
                              void* d_out, int out_size) {
    const float4* rgba = (const float4*)d_in[0];
    const float*  dist = (const float*)d_in[1];
    float* out = (float*)d_out;

    dim3 block(256);
    dim3 grid((NR_RAYS * 32) / 256);   // 1 warp per ray
    composite_kernel<<<grid, block>>>(rgba, dist, out);
}

// round 4
// speedup vs baseline: 1.2668x; 1.0164x over previous
#include <cuda_runtime.h>

// TensorReduce_88536455839845 — NeRF over-compositing, R3.
// One warp per ray. Key change vs R2: __launch_bounds__(256, 4) releases the
// register cap (32 -> ~64) so ptxas can keep ALL 12 global loads front-batched
// (true MLP=12/thread) instead of sinking them into the scan dependency chain.
//
// rgba:     [65536, 192, 4] f32  (d_in[0])
// distance: [65536, 192]    f32  (d_in[1])
// out:      [65536, 3]      f32

#define NR_RAYS    65536
#define NR_SAMPLES 192
#define NR_CHUNKS  6

#define EPS_DIST   1e-5f
#define EPS_ALPHA  1e-8f
#define FAR_DELTA  1e4f

__device__ __forceinline__ float fast_sigmoid(float x) {
    return __fdividef(1.0f, 1.0f + __expf(-x));
}

__global__ __launch_bounds__(256, 4) void composite_kernel(
    const float4* __restrict__ rgba,     // [N, S] float4
    const float*  __restrict__ dist,     // [N, S]
    float*        __restrict__ out)      // [N, 3]
{
    const unsigned FULL = 0xffffffffu;
    int gwarp = (blockIdx.x * blockDim.x + threadIdx.x) >> 5;
    int lane  = threadIdx.x & 31;
    if (gwarp >= NR_RAYS) return;

    const float4* ray_rgba = rgba + (size_t)gwarp * NR_SAMPLES;
    const float*  ray_dist = dist + (size_t)gwarp * NR_SAMPLES;

    // ---- Phase 1: ALL global loads up front (streaming, evict-first) ----
    // With the 64-reg budget these live in registers; 12 outstanding
    // loads/thread fully cover DRAM latency.
    float4 v[NR_CHUNKS];
    float  d0[NR_CHUNKS];
    #pragma unroll
    for (int k = 0; k < NR_CHUNKS; ++k) {
        int s = (k << 5) + lane;
        v[k]  = __ldcs(&ray_rgba[s]);
        d0[k] = __ldcs(&ray_dist[s]);
    }

    // ---- Phase 2: alpha / (1-alpha+eps) per chunk ----
    float alpha[NR_CHUNKS];
    float incl[NR_CHUNKS];
    #pragma unroll
    for (int k = 0; k < NR_CHUNKS; ++k) {
        // d[s+1]: neighbor lane's value; lane 31 takes next chunk's lane 0.
        float nxt = (k < NR_CHUNKS - 1) ? __shfl_sync(FULL, d0[k + 1], 0) : d0[k];
        float d1  = __shfl_down_sync(FULL, d0[k], 1);
        if (lane == 31) d1 = nxt;

        bool  last  = (k == NR_CHUNKS - 1) && (lane == 31);
        float delta = last ? FAR_DELTA : fabsf(d1 - d0[k]);

        float density = (d0[k] < EPS_DIST) ? 0.0f : fmaxf(v[k].w, 0.0f);

        float a  = 1.0f - __expf(-delta * density);
        alpha[k] = a;
        incl[k]  = 1.0f - a + EPS_ALPHA;        // strictly > 0
    }

    // ---- Phase 3: 6 independent inclusive product scans, interleaved ----
    // Outer loop over shuffle offset -> 6-wide ILP on the SHFL latency chain.
    #pragma unroll
    for (int off = 1; off < 32; off <<= 1) {
        #pragma unroll
        for (int k = 0; k < NR_CHUNKS; ++k) {
            float t = __shfl_up_sync(FULL, incl[k], off);
            if (lane >= off) incl[k] *= t;
        }
    }

    // Exclusive value + per-chunk totals (all independent)
    float excl[NR_CHUNKS], tot[NR_CHUNKS];
    #pragma unroll
    for (int k = 0; k < NR_CHUNKS; ++k) {
        float e = __shfl_up_sync(FULL, incl[k], 1);
        excl[k] = (lane == 0) ? 1.0f : e;
        tot[k]  = __shfl_sync(FULL, incl[k], 31);
    }

    // ---- Phase 4: carry chain (6 dependent FMULs) + weighted accumulate ----
    float carry = 1.0f;
    float r_acc = 0.0f, g_acc = 0.0f, b_acc = 0.0f;
    #pragma unroll
    for (int k = 0; k < NR_CHUNKS; ++k) {
        float w = alpha[k] * carry * excl[k];
        r_acc = fmaf(w, fast_sigmoid(v[k].x), r_acc);
        g_acc = fmaf(w, fast_sigmoid(v[k].y), g_acc);
        b_acc = fmaf(w, fast_sigmoid(v[k].z), b_acc);
        carry *= tot[k];
    }

    // ---- Warp tree-reduce the 3 accumulators ----
    #pragma unroll
    for (int off = 16; off > 0; off >>= 1) {
        r_acc += __shfl_down_sync(FULL, r_acc, off);
        g_acc += __shfl_down_sync(FULL, g_acc, off);
        b_acc += __shfl_down_sync(FULL, b_acc, off);
    }

    if (lane == 0) {
        float* o = out + (size_t)gwarp * 3;
        o[0] = r_acc;
        o[1] = g_acc;
        o[2] = b_acc;
    }
}

extern "C" void kernel_launch(void* const* d_in, const int* in_sizes, int n_in,
                              void* d_out, int out_size) {
    const float4* rgba = (const float4*)d_in[0];
    const float*  dist = (const float*)d_in[1];
    float* out = (float*)d_out;

    dim3 block(256);
    dim3 grid((NR_RAYS * 32) / 256);   // 1 warp per ray
    composite_kernel<<<grid, block>>>(rgba, dist, out);
}